// round 9
// baseline (speedup 1.0000x reference)
#include <cuda_runtime.h>
#include <cuda_bf16.h>
#include <stdint.h>
#include <math.h>

#define B_ 4
#define S_ 2048
#define T_ 2048
#define C_ 256
#define BST 16777216  // B_*S_*T_
#define XN  2097152   // B_*S_*C_
#define PN  4194304   // 2*B_*S_*C_

// ---- tcgen05 only legal when an sm_103a feature pass exists ----
#if defined(__CUDA_ARCH__) && defined(__CUDA_ARCH_FEAT_SM103_ALL)
#define HAS_TC 1
#else
#define HAS_TC 0
#endif

// ---------------- scratch (device globals; no runtime allocation) -------------
__device__ __nv_bfloat16 g_Xhi[PN];
__device__ __nv_bfloat16 g_Xlo[PN];
__device__ __nv_bfloat16 g_Whi[C_*C_];
__device__ __nv_bfloat16 g_Wlo[C_*C_];
__device__ __nv_bfloat16 g_Phi[PN];
__device__ __nv_bfloat16 g_Plo[PN];
__device__ float         g_sim[BST];

__device__ float g_Mrow[B_*S_], g_rZrow[B_*S_], g_Rmax[B_*S_];
__device__ float g_Mcol[B_*T_], g_rZcol[B_*T_], g_Cmax[B_*T_];
__device__ float g_pM[B_*64*T_], g_pZ[B_*64*T_];
__device__ unsigned char g_smask[B_*S_], g_tmask[B_*T_];

// ============================ PTX helpers =====================================
__device__ __forceinline__ uint32_t smem_u32(const void* p) {
    uint32_t a;
    asm("{ .reg .u64 t; cvta.to.shared.u64 t, %1; cvt.u32.u64 %0, t; }" : "=r"(a) : "l"(p));
    return a;
}
__device__ __forceinline__ void cp16(uint32_t dst, const void* src) {
    asm volatile("cp.async.cg.shared.global [%0], [%1], 16;\n" :: "r"(dst), "l"(src));
}
#define CP_COMMIT()  asm volatile("cp.async.commit_group;\n" ::: "memory")

#define MMA3(d,a,b) asm volatile( \
    "mma.sync.aligned.m16n8k16.row.col.f32.bf16.bf16.f32 " \
    "{%0,%1,%2,%3},{%4,%5,%6,%7},{%8,%9},{%0,%1,%2,%3};" \
    : "+f"(d[0]),"+f"(d[1]),"+f"(d[2]),"+f"(d[3]) \
    : "r"(a[0]),"r"(a[1]),"r"(a[2]),"r"(a[3]),"r"(b[0]),"r"(b[1]))

#if HAS_TC
#define TC_ALLOC(smem_addr, n)   asm volatile("tcgen05.alloc.cta_group::1.sync.aligned.shared::cta.b32 [%0], %1;" :: "r"(smem_addr), "r"((uint32_t)(n)) : "memory")
#define TC_DEALLOC(tmem, n)      asm volatile("tcgen05.dealloc.cta_group::1.sync.aligned.b32 %0, %1;" :: "r"(tmem), "r"((uint32_t)(n)))
#define TC_RELINQ()              asm volatile("tcgen05.relinquish_alloc_permit.cta_group::1.sync.aligned;")
#define TC_COMMIT(mbar)          asm volatile("tcgen05.commit.cta_group::1.mbarrier::arrive::one.shared::cluster.b64 [%0];" :: "r"(mbar) : "memory")
#define TC_FENCE_AFTER()         asm volatile("tcgen05.fence::after_thread_sync;" ::: "memory")
#define TC_WAIT_LD()             asm volatile("tcgen05.wait::ld.sync.aligned;" ::: "memory")
#define FENCE_ASYNC_SHARED()     asm volatile("fence.proxy.async.shared::cta;" ::: "memory")
#define MBAR_INIT(a, c)          asm volatile("mbarrier.init.shared.b64 [%0], %1;" :: "r"(a), "r"((uint32_t)(c)) : "memory")
#define MBAR_INVAL(a)            asm volatile("mbarrier.inval.shared.b64 [%0];" :: "r"(a) : "memory")

#define MBAR_WAIT(a, par) do { \
    uint32_t _m = (a), _p = (par), _d; \
    asm volatile("{\n\t.reg .pred p;\n\t" \
        "mbarrier.try_wait.parity.acquire.cta.shared::cta.b64 p, [%1], %2;\n\t" \
        "selp.b32 %0, 1, 0, p;\n\t}" : "=r"(_d) : "r"(_m), "r"(_p) : "memory"); \
    if (!_d) { \
        asm volatile("{\n\t.reg .pred P1;\n\t" \
            "WL_%=:\n\t" \
            "mbarrier.try_wait.parity.acquire.cta.shared::cta.b64 P1, [%0], %1, 0x989680;\n\t" \
            "@P1 bra.uni WD_%=;\n\t" \
            "bra.uni WL_%=;\n\t" \
            "WD_%=:\n\t}" :: "r"(_m), "r"(_p) : "memory"); \
    } \
} while (0)

#define LDTM_X32(r, addr) \
    asm volatile("tcgen05.ld.sync.aligned.32x32b.x32.b32 " \
        "{%0,%1,%2,%3,%4,%5,%6,%7,%8,%9,%10,%11,%12,%13,%14,%15," \
        "%16,%17,%18,%19,%20,%21,%22,%23,%24,%25,%26,%27,%28,%29,%30,%31}, [%32];" \
        : "=r"((r)[0]), "=r"((r)[1]), "=r"((r)[2]), "=r"((r)[3]), \
          "=r"((r)[4]), "=r"((r)[5]), "=r"((r)[6]), "=r"((r)[7]), \
          "=r"((r)[8]), "=r"((r)[9]), "=r"((r)[10]), "=r"((r)[11]), \
          "=r"((r)[12]), "=r"((r)[13]), "=r"((r)[14]), "=r"((r)[15]), \
          "=r"((r)[16]), "=r"((r)[17]), "=r"((r)[18]), "=r"((r)[19]), \
          "=r"((r)[20]), "=r"((r)[21]), "=r"((r)[22]), "=r"((r)[23]), \
          "=r"((r)[24]), "=r"((r)[25]), "=r"((r)[26]), "=r"((r)[27]), \
          "=r"((r)[28]), "=r"((r)[29]), "=r"((r)[30]), "=r"((r)[31]) \
        : "r"(addr))

__device__ __forceinline__ uint32_t elect_one() {
    uint32_t p;
    asm volatile("{\n\t.reg .pred e;\n\telect.sync _|e, 0xFFFFFFFF;\n\t"
                 "selp.b32 %0, 1, 0, e;\n\t}" : "=r"(p));
    return p;
}
__device__ __forceinline__ uint64_t mk_desc(uint32_t addr) {
    const uint64_t base =
        (uint64_t(2) << 61) | (uint64_t(1) << 46) | (uint64_t(64) << 32) | (uint64_t(1) << 16);
    return base | ((uint64_t)(addr >> 4) & 0x3FFF);
}
__device__ __forceinline__ void umma_bf16_ss(uint32_t d, uint64_t a, uint64_t b,
                                             uint32_t idesc, uint32_t en) {
    asm volatile(
        "{\n\t.reg .pred p;\n\t"
        "setp.ne.u32 p, %4, 0;\n\t"
        "tcgen05.mma.cta_group::1.kind::f16 [%0], %1, %2, %3, {%5,%5,%5,%5}, p;\n\t}"
        :: "r"(d), "l"(a), "l"(b), "r"(idesc), "r"(en), "r"(0u)
        : "memory");
}
// fp32 accum, bf16 A/B, N=128, M=128
#define SIM_IDESC128 0x8200490u
#endif  // HAS_TC

// ---------------- mask decode (1-byte bool vs 4-byte encodings) ----------------
__global__ void k_masks(const unsigned char* __restrict__ sm,
                        const unsigned char* __restrict__ tm) {
    int i = blockIdx.x * blockDim.x + threadIdx.x;
    if (i >= B_*S_) return;
    bool ws = (sm[1] == 0);
    bool wt = (tm[1] == 0);
    g_smask[i] = ws ? (((const int*)sm)[i] != 0) : (sm[i] != 0);
    g_tmask[i] = wt ? (((const int*)tm)[i] != 0) : (tm[i] != 0);
}

// ---------------- fused fp32 -> (bf16 hi, lo) splits for src, tgt, W -----------
__global__ void k_prep3(const float* __restrict__ src, const float* __restrict__ tgt,
                        const float* __restrict__ W) {
    int i = blockIdx.x * blockDim.x + threadIdx.x;
    const float* x; __nv_bfloat16 *hi, *lo; int off;
    if (i < XN)            { x = src; off = i;          hi = g_Xhi;      lo = g_Xlo; }
    else if (i < 2*XN)     { x = tgt; off = i - XN;     hi = g_Xhi + XN; lo = g_Xlo + XN; }
    else if (i < 2*XN + C_*C_) { x = W; off = i - 2*XN; hi = g_Whi;      lo = g_Wlo; }
    else return;
    float v = x[off];
    __nv_bfloat16 h = __float2bfloat16(v);
    hi[off] = h;
    lo[off] = __float2bfloat16(v - __bfloat162float(h));
}

// ========= 3-term split-bf16 GEMM fallback (mma.sync, skips when TC is live) ====
#define GEMM_SMEM 81920

template<int SKIP_IF_TC>
__global__ __launch_bounds__(256, 1) void k_gemm(
    const __nv_bfloat16* __restrict__ Ahi, const __nv_bfloat16* __restrict__ Alo, long long aStr,
    const __nv_bfloat16* __restrict__ Bhi, const __nv_bfloat16* __restrict__ Blo, long long bStr,
    float* __restrict__ Cf, __nv_bfloat16* __restrict__ Chi, __nv_bfloat16* __restrict__ Clo,
    long long cStr, int N, int K, float scale)
{
#if HAS_TC
    if (SKIP_IF_TC) return;
#endif
    extern __shared__ uint32_t sm4[];
    const int tid  = threadIdx.x;
    const int lane = tid & 31, wid = tid >> 5;
    const int wm = wid & 3, wn = wid >> 2;
    const int bn = blockIdx.x, bm = blockIdx.y, z = blockIdx.z;
    const int ld32 = K >> 1;
    const int NKT = K >> 5;

    const uint32_t* A32h = (const uint32_t*)(Ahi + (size_t)z * aStr) + (size_t)bm * 128 * ld32;
    const uint32_t* A32l = (const uint32_t*)(Alo + (size_t)z * aStr) + (size_t)bm * 128 * ld32;
    const uint32_t* B32h = (const uint32_t*)(Bhi + (size_t)z * bStr) + (size_t)bn * 128 * ld32;
    const uint32_t* B32l = (const uint32_t*)(Blo + (size_t)z * bStr) + (size_t)bn * 128 * ld32;

    const uint32_t smemB = smem_u32(sm4);

    float acc[2][8][4];
#pragma unroll
    for (int a = 0; a < 2; a++)
#pragma unroll
        for (int b = 0; b < 8; b++)
#pragma unroll
            for (int c = 0; c < 4; c++) acc[a][b][c] = 0.f;

    auto loadStage = [&](int st, int kt) {
        const int row0 = tid >> 2;
        const int part = tid & 3;
#pragma unroll
        for (int j = 0; j < 8; j++) {
            const uint32_t* base = (j < 2) ? A32h : (j < 4) ? A32l : (j < 6) ? B32h : B32l;
            int row = ((j & 1) << 6) + row0;
            const uint32_t* s = base + (size_t)row * ld32 + kt * 16 + part * 4;
            uint32_t d = smemB + st * 40960 + (j >> 1) * 10240 + row * 80 + part * 16;
            cp16(d, s);
        }
        CP_COMMIT();
    };

    auto compute = [&](int st) {
        const uint32_t* base = sm4 + st * 10240;
        const uint32_t* Ah = base;
        const uint32_t* Al = base + 2560;
        const uint32_t* Bh = base + 5120;
        const uint32_t* Bl = base + 7680;
#pragma unroll
        for (int ks = 0; ks < 2; ks++) {
            const int kb = ks * 8;
            uint32_t ah[2][4], al[2][4], bh[8][2], bl[8][2];
#pragma unroll
            for (int mt = 0; mt < 2; mt++) {
                int i0 = (wm * 32 + mt * 16 + (lane >> 2)) * 20 + kb + (lane & 3);
                ah[mt][0] = Ah[i0];     ah[mt][1] = Ah[i0 + 160];
                ah[mt][2] = Ah[i0 + 4]; ah[mt][3] = Ah[i0 + 164];
                al[mt][0] = Al[i0];     al[mt][1] = Al[i0 + 160];
                al[mt][2] = Al[i0 + 4]; al[mt][3] = Al[i0 + 164];
            }
#pragma unroll
            for (int nt = 0; nt < 8; nt++) {
                int i0 = (wn * 64 + nt * 8 + (lane >> 2)) * 20 + kb + (lane & 3);
                bh[nt][0] = Bh[i0]; bh[nt][1] = Bh[i0 + 4];
                bl[nt][0] = Bl[i0]; bl[nt][1] = Bl[i0 + 4];
            }
#pragma unroll
            for (int mt = 0; mt < 2; mt++)
#pragma unroll
                for (int nt = 0; nt < 8; nt++) {
                    MMA3(acc[mt][nt], ah[mt], bh[nt]);
                    MMA3(acc[mt][nt], al[mt], bh[nt]);
                    MMA3(acc[mt][nt], ah[mt], bl[nt]);
                }
        }
    };

    loadStage(0, 0);
    for (int kt = 0; kt < NKT; ++kt) {
        asm volatile("cp.async.wait_group 0;\n" ::: "memory");
        __syncthreads();
        if (kt + 1 < NKT) loadStage((kt + 1) & 1, kt + 1);
        compute(kt & 1);
        __syncthreads();
    }

    if (Chi == nullptr) {
        float* Cp = Cf + (size_t)z * cStr + (size_t)(bm * 128) * N + bn * 128;
#pragma unroll
        for (int mt = 0; mt < 2; ++mt) {
            int r0 = wm * 32 + mt * 16 + (lane >> 2);
#pragma unroll
            for (int nt = 0; nt < 8; ++nt) {
                int c0 = wn * 64 + nt * 8 + (lane & 3) * 2;
                float2 v0 = make_float2(acc[mt][nt][0] * scale, acc[mt][nt][1] * scale);
                float2 v1 = make_float2(acc[mt][nt][2] * scale, acc[mt][nt][3] * scale);
                *reinterpret_cast<float2*>(Cp + (size_t)r0 * N + c0) = v0;
                *reinterpret_cast<float2*>(Cp + (size_t)(r0 + 8) * N + c0) = v1;
            }
        }
    } else {
        size_t ro = (size_t)z * cStr + (size_t)(bm * 128) * N + bn * 128;
#pragma unroll
        for (int mt = 0; mt < 2; ++mt) {
            int r0 = wm * 32 + mt * 16 + (lane >> 2);
#pragma unroll
            for (int nt = 0; nt < 8; ++nt) {
                int c0 = wn * 64 + nt * 8 + (lane & 3) * 2;
#pragma unroll
                for (int h = 0; h < 2; h++) {
                    float v0 = acc[mt][nt][h * 2 + 0] * scale;
                    float v1 = acc[mt][nt][h * 2 + 1] * scale;
                    __nv_bfloat16 h0 = __float2bfloat16(v0);
                    __nv_bfloat16 h1 = __float2bfloat16(v1);
                    __nv_bfloat16 l0 = __float2bfloat16(v0 - __bfloat162float(h0));
                    __nv_bfloat16 l1 = __float2bfloat16(v1 - __bfloat162float(h1));
                    size_t off = ro + (size_t)(r0 + h * 8) * N + c0;
                    __nv_bfloat162 hp; hp.x = h0; hp.y = h1;
                    __nv_bfloat162 lp; lp.x = l0; lp.y = l1;
                    *reinterpret_cast<__nv_bfloat162*>(Chi + off) = hp;
                    *reinterpret_cast<__nv_bfloat162*>(Clo + off) = lp;
                }
            }
        }
    }
}

// ============ tcgen05 GEMM: resident A + 2 interleaved N=128 tiles =================
// MODE 0 (sim):  grid (8,16,4); A = P-src rows, B = P-tgt rows, out = sim (fp32, x scale)
// MODE 1 (proj): grid (128);    A = X rows,     B = W,          out = Phi/Plo (split, x scale)
// A resident: 8 tiles (hi kc0-3, lo kc0-3) x 16KB. B: 16 chunks (c=2q+tc) of 16KB
// through 6 slots; two TMEM D tiles (cols 0/128); 2 alternating mbarriers.
#define SIM_SMEM  230400
#define OFF_B     131072

template<int MODE>
__global__ __launch_bounds__(256, 1)
void k_tc(const __nv_bfloat16* __restrict__ Ah_g, const __nv_bfloat16* __restrict__ Al_g,
          const __nv_bfloat16* __restrict__ Bh_g, const __nv_bfloat16* __restrict__ Bl_g,
          float* __restrict__ simout, __nv_bfloat16* __restrict__ PhO,
          __nv_bfloat16* __restrict__ PlO, float scale)
{
#if HAS_TC
    extern __shared__ char ds[];
    __shared__ uint32_t s_tptr;
    __shared__ __align__(16) uint64_t s_mbar[2];

    const int tid = threadIdx.x, lane = tid & 31, wid = tid >> 5;
    const int bn = blockIdx.x, bm = (MODE == 0) ? blockIdx.y : blockIdx.x;
    const int z  = blockIdx.z;
    const uint32_t dsb = (smem_u32(ds) + 1023u) & ~1023u;   // SW128 needs 1024-aligned
    const uint32_t mb0 = smem_u32(&s_mbar[0]);
    const uint32_t mb1 = smem_u32(&s_mbar[1]);

    const char *Ahsrc, *Alsrc, *Bhsrc, *Blsrc;
    if (MODE == 0) {
        Ahsrc = (const char*)(Ah_g + ((size_t)z * S_ + bm * 128) * C_);
        Alsrc = (const char*)(Al_g + ((size_t)z * S_ + bm * 128) * C_);
        Bhsrc = (const char*)(Bh_g + ((size_t)z * T_ + bn * 256) * C_);
        Blsrc = (const char*)(Bl_g + ((size_t)z * T_ + bn * 256) * C_);
    } else {
        Ahsrc = (const char*)(Ah_g + (size_t)bm * 128 * C_);
        Alsrc = (const char*)(Al_g + (size_t)bm * 128 * C_);
        Bhsrc = (const char*)Bh_g;
        Blsrc = (const char*)Bl_g;
    }

    if (wid == 0) TC_ALLOC(smem_u32(&s_tptr), 256);
    if (tid == 0) { MBAR_INIT(mb0, 1); MBAR_INIT(mb1, 1); }
    __syncthreads();
    const uint32_t tmem = s_tptr;

    auto loadA = [&]() {
#pragma unroll
        for (int j = 0; j < 32; j++) {
            int c = tid + j * 256;
            int tile = c >> 10, idx = c & 1023;
            int row = idx >> 3, seg = idx & 7;
            const char* base = (tile < 4) ? Ahsrc : Alsrc;
            int kc = tile & 3;
            const char* s = base + (size_t)row * 512 + kc * 128 + seg * 16;
            uint32_t boff = (uint32_t)(row * 128 + seg * 16) ^ ((uint32_t)(row & 7) << 4);
            cp16(dsb + tile * 16384 + boff, s);
        }
        CP_COMMIT();
    };

    auto loadB = [&](int c) {   // chunk c: tc=c&1 (tile), q=c>>1 (0-3 hi, 4-7 lo)
        const int tc = c & 1, q = c >> 1, kc = q & 3, slot = c % 6;
        const char* base = ((q < 4) ? Bhsrc : Blsrc) + (size_t)tc * 128 * 512;
#pragma unroll
        for (int j = 0; j < 4; j++) {
            int cx = tid + j * 256;
            int row = cx >> 3, seg = cx & 7;
            const char* s = base + (size_t)row * 512 + kc * 128 + seg * 16;
            uint32_t boff = (uint32_t)(row * 128 + seg * 16) ^ ((uint32_t)(row & 7) << 4);
            cp16(dsb + OFF_B + slot * 16384 + boff, s);
        }
        CP_COMMIT();
    };

    loadB(0);
    loadA();
    loadB(1); loadB(2); loadB(3); loadB(4); loadB(5);

#pragma unroll
    for (int c = 0; c < 16; c++) {
        if (c >= 2) {
            const int k = c - 2;
            MBAR_WAIT((k & 1) ? mb1 : mb0, (k >> 1) & 1);
        }
        if (c >= 2 && c <= 11) loadB(c + 4);
        if (c == 0)       asm volatile("cp.async.wait_group 5;\n" ::: "memory");
        else if (c <= 11) asm volatile("cp.async.wait_group 4;\n" ::: "memory");
        else if (c == 12) asm volatile("cp.async.wait_group 3;\n" ::: "memory");
        else if (c == 13) asm volatile("cp.async.wait_group 2;\n" ::: "memory");
        else if (c == 14) asm volatile("cp.async.wait_group 1;\n" ::: "memory");
        else              asm volatile("cp.async.wait_group 0;\n" ::: "memory");
        __syncthreads();
        if (wid == 0) {
            if (elect_one()) {
                FENCE_ASYNC_SHARED();
                const int tc = c & 1, q = c >> 1, kc = q & 3, slot = c % 6;
                uint64_t ah = mk_desc(dsb + kc * 16384);
                uint64_t al = mk_desc(dsb + 65536 + kc * 16384);
                uint64_t bd = mk_desc(dsb + OFF_B + slot * 16384);
                uint32_t D = tmem + tc * 128;
                if (q < 4) {
#pragma unroll
                    for (int ks = 0; ks < 4; ks++) {
                        umma_bf16_ss(D, ah + ks * 2, bd + ks * 2, SIM_IDESC128,
                                     (q > 0) || (ks > 0));
                        umma_bf16_ss(D, al + ks * 2, bd + ks * 2, SIM_IDESC128, 1u);
                    }
                } else {
#pragma unroll
                    for (int ks = 0; ks < 4; ks++)
                        umma_bf16_ss(D, ah + ks * 2, bd + ks * 2, SIM_IDESC128, 1u);
                }
                TC_COMMIT((c & 1) ? mb1 : mb0);
            }
        }
    }
    MBAR_WAIT(mb0, 1);
    MBAR_WAIT(mb1, 1);

    TC_FENCE_AFTER();
    const int sub = wid & 3, half = (wid >> 2) * 128;
    if (MODE == 0) {
        float* out = simout + ((size_t)z * S_ + bm * 128 + sub * 32 + lane) * T_
                     + bn * 256 + half;
#pragma unroll
        for (int cb = 0; cb < 4; cb++) {
            uint32_t r[32];
            LDTM_X32(r, tmem + half + cb * 32);
            TC_WAIT_LD();
#pragma unroll
            for (int i = 0; i < 8; i++) {
                float4 v = make_float4(__uint_as_float(r[i*4+0]) * scale,
                                       __uint_as_float(r[i*4+1]) * scale,
                                       __uint_as_float(r[i*4+2]) * scale,
                                       __uint_as_float(r[i*4+3]) * scale);
                *reinterpret_cast<float4*>(out + cb * 32 + i * 4) = v;
            }
        }
    } else {
        size_t g = (size_t)(bm * 128 + sub * 32 + lane) * C_ + half;
#pragma unroll
        for (int cb = 0; cb < 4; cb++) {
            uint32_t r[32];
            LDTM_X32(r, tmem + half + cb * 32);
            TC_WAIT_LD();
#pragma unroll
            for (int i = 0; i < 8; i++) {
                float v0 = __uint_as_float(r[i*4+0]) * scale;
                float v1 = __uint_as_float(r[i*4+1]) * scale;
                float v2 = __uint_as_float(r[i*4+2]) * scale;
                float v3 = __uint_as_float(r[i*4+3]) * scale;
                __nv_bfloat16 h0 = __float2bfloat16(v0), h1 = __float2bfloat16(v1);
                __nv_bfloat16 h2 = __float2bfloat16(v2), h3 = __float2bfloat16(v3);
                __nv_bfloat162 hp01; hp01.x = h0; hp01.y = h1;
                __nv_bfloat162 hp23; hp23.x = h2; hp23.y = h3;
                __nv_bfloat162 lp01, lp23;
                lp01.x = __float2bfloat16(v0 - __bfloat162float(h0));
                lp01.y = __float2bfloat16(v1 - __bfloat162float(h1));
                lp23.x = __float2bfloat16(v2 - __bfloat162float(h2));
                lp23.y = __float2bfloat16(v3 - __bfloat162float(h3));
                size_t off = g + cb * 32 + i * 4;
                *reinterpret_cast<__nv_bfloat162*>(PhO + off)     = hp01;
                *reinterpret_cast<__nv_bfloat162*>(PhO + off + 2) = hp23;
                *reinterpret_cast<__nv_bfloat162*>(PlO + off)     = lp01;
                *reinterpret_cast<__nv_bfloat162*>(PlO + off + 2) = lp23;
            }
        }
    }

    __syncthreads();
    if (tid == 0) { MBAR_INVAL(mb0); MBAR_INVAL(mb1); }
    __syncthreads();
    if (wid == 0) { TC_RELINQ(); TC_DEALLOC(tmem, 256); }
#else
    (void)Ah_g; (void)Al_g; (void)Bh_g; (void)Bl_g;
    (void)simout; (void)PhO; (void)PlO; (void)scale;
#endif
}

// ---------------- block reductions ------------------------------------------------
__device__ __forceinline__ float bredMax(float v, float* sh) {
#pragma unroll
    for (int o = 16; o; o >>= 1) v = fmaxf(v, __shfl_xor_sync(0xffffffffu, v, o));
    if ((threadIdx.x & 31) == 0) sh[threadIdx.x >> 5] = v;
    __syncthreads();
    float r = sh[0];
#pragma unroll
    for (int i = 1; i < 8; i++) r = fmaxf(r, sh[i]);
    __syncthreads();
    return r;
}
__device__ __forceinline__ float bredSum(float v, float* sh) {
#pragma unroll
    for (int o = 16; o; o >>= 1) v += __shfl_xor_sync(0xffffffffu, v, o);
    if ((threadIdx.x & 31) == 0) sh[threadIdx.x >> 5] = v;
    __syncthreads();
    float r = sh[0];
#pragma unroll
    for (int i = 1; i < 8; i++) r += sh[i];
    __syncthreads();
    return r;
}

// ---------------- fused row stats (tgt-masked) + col partials (src-masked) -------
__global__ __launch_bounds__(256) void k_stats() {
    int b = blockIdx.y, ch = blockIdx.x, tid = threadIdx.x;
    int t0 = tid * 8;
    __shared__ float sh[8];
    bool tm[8]; float colM[8], colZ[8];
#pragma unroll
    for (int i = 0; i < 8; i++) {
        tm[i] = g_tmask[b * T_ + t0 + i];
        colM[i] = -INFINITY; colZ[i] = 0.f;
    }
    for (int r = 0; r < 32; r++) {
        int s = ch * 32 + r;
        const float4* row = (const float4*)(g_sim + ((size_t)b * S_ + s) * T_ + t0);
        float4 v0 = row[0], v1 = row[1];
        float x[8] = {v0.x, v0.y, v0.z, v0.w, v1.x, v1.y, v1.z, v1.w};
        float m = -INFINITY;
#pragma unroll
        for (int i = 0; i < 8; i++) if (tm[i]) m = fmaxf(m, x[i]);
        m = bredMax(m, sh);
        float zz = 0.f;
#pragma unroll
        for (int i = 0; i < 8; i++) if (tm[i]) zz += __expf(x[i] - m);
        zz = bredSum(zz, sh);
        if (tid == 0) { g_Mrow[b * S_ + s] = m; g_rZrow[b * S_ + s] = 1.f / zz; }
        if (g_smask[b * S_ + s]) {
#pragma unroll
            for (int i = 0; i < 8; i++) {
                float mn = fmaxf(colM[i], x[i]);
                colZ[i] = colZ[i] * __expf(colM[i] - mn) + __expf(x[i] - mn);
                colM[i] = mn;
            }
        }
    }
    size_t o = (size_t)(b * 64 + ch) * T_ + t0;
#pragma unroll
    for (int i = 0; i < 8; i++) { g_pM[o + i] = colM[i]; g_pZ[o + i] = colZ[i]; }
}

__global__ void k_colcomb() {
    int i = blockIdx.x * blockDim.x + threadIdx.x;
    if (i >= B_ * T_) return;
    int b = i >> 11, t = i & 2047;
    float M = -INFINITY;
    for (int c = 0; c < 64; c++) M = fmaxf(M, g_pM[(size_t)(b * 64 + c) * T_ + t]);
    float Z = 0.f;
    for (int c = 0; c < 64; c++) {
        float m = g_pM[(size_t)(b * 64 + c) * T_ + t];
        Z += g_pZ[(size_t)(b * 64 + c) * T_ + t] * __expf(m - M);
    }
    g_Mcol[i] = M; g_rZcol[i] = 1.f / Z;
}

// ---------------- conf + per-row max + col-max partials (fused) -------------------
__global__ __launch_bounds__(256) void k_conf(float* __restrict__ conf) {
    int b = blockIdx.y, ch = blockIdx.x, tid = threadIdx.x;
    int t0 = tid * 8;
    __shared__ float sh[8];
    float mc[8], rzc[8], cm[8]; bool tm[8];
#pragma unroll
    for (int i = 0; i < 8; i++) {
        mc[i] = g_Mcol[b * T_ + t0 + i];
        rzc[i] = g_rZcol[b * T_ + t0 + i];
        tm[i] = g_tmask[b * T_ + t0 + i];
        cm[i] = 0.f;
    }
    for (int r = 0; r < 32; r++) {
        int s = ch * 32 + r;
        bool sv = g_smask[b * S_ + s];
        float Mr = g_Mrow[b * S_ + s], rZr = g_rZrow[b * S_ + s];
        size_t off = ((size_t)b * S_ + s) * T_ + t0;
        const float4* row = (const float4*)(g_sim + off);
        float4 v0 = row[0], v1 = row[1];
        float x[8] = {v0.x, v0.y, v0.z, v0.w, v1.x, v1.y, v1.z, v1.w};
        float v[8]; float rm = 0.f;
#pragma unroll
        for (int i = 0; i < 8; i++) {
            float val = 0.f;
            if (sv && tm[i])
                val = __expf(2.f * x[i] - Mr - mc[i]) * rZr * rzc[i];
            v[i] = val;
            rm = fmaxf(rm, val);
            cm[i] = fmaxf(cm[i], val);
        }
        float4 o0 = make_float4(v[0], v[1], v[2], v[3]);
        float4 o1 = make_float4(v[4], v[5], v[6], v[7]);
        float4* outp = (float4*)(conf + off);
        outp[0] = o0; outp[1] = o1;
        rm = bredMax(rm, sh);
        if (tid == 0) g_Rmax[b * S_ + s] = rm;
    }
    size_t o = (size_t)(b * 64 + ch) * T_ + t0;
#pragma unroll
    for (int i = 0; i < 8; i++) g_pM[o + i] = cm[i];
}

__global__ void k_cmaxcomb() {
    int i = blockIdx.x * blockDim.x + threadIdx.x;
    if (i >= B_ * T_) return;
    int b = i >> 11, t = i & 2047;
    float m = 0.f;
    for (int c = 0; c < 64; c++) m = fmaxf(m, g_pM[(size_t)(b * 64 + c) * T_ + t]);
    g_Cmax[i] = m;
}

// ---------------- mutual-max + threshold mask -------------------------------------
__global__ void k_m(const float* __restrict__ conf, float* __restrict__ mf,
                    unsigned char* __restrict__ mb, int mode) {
    int b = blockIdx.y, s = blockIdx.x, tid = threadIdx.x;
    size_t roff = ((size_t)b * S_ + s) * T_;
    float rm = g_Rmax[b * S_ + s];
#pragma unroll
    for (int i = 0; i < 8; i++) {
        int t = tid + i * 256;
        float v = conf[roff + t];
        bool hit = (v > 0.2f) && (v == rm) && (v == g_Cmax[b * T_ + t]);
        if (mode == 0) mf[roff + t] = hit ? 1.f : 0.f;
        else           mb[roff + t] = hit ? 1 : 0;
    }
}

// ---------------- launch -------------------------------------------------------------
extern "C" void kernel_launch(void* const* d_in, const int* in_sizes, int n_in,
                              void* d_out, int out_size) {
    const float *src = nullptr, *tgt = nullptr, *W = nullptr;
    const unsigned char *smk = nullptr, *tmk = nullptr;
    for (int i = 0; i < n_in; i++) {
        if (in_sizes[i] == XN)        { if (!src) src = (const float*)d_in[i]; else tgt = (const float*)d_in[i]; }
        else if (in_sizes[i] == 8192) { if (!smk) smk = (const unsigned char*)d_in[i]; else tmk = (const unsigned char*)d_in[i]; }
        else if (in_sizes[i] == 65536) W = (const float*)d_in[i];
    }

    void *xhi, *xlo, *whi, *wlo, *phi, *plo, *sim;
    cudaGetSymbolAddress(&xhi, g_Xhi);  cudaGetSymbolAddress(&xlo, g_Xlo);
    cudaGetSymbolAddress(&whi, g_Whi);  cudaGetSymbolAddress(&wlo, g_Wlo);
    cudaGetSymbolAddress(&phi, g_Phi);  cudaGetSymbolAddress(&plo, g_Plo);
    cudaGetSymbolAddress(&sim, g_sim);

    __nv_bfloat16* Xhi = (__nv_bfloat16*)xhi;  __nv_bfloat16* Xlo = (__nv_bfloat16*)xlo;
    __nv_bfloat16* Whi = (__nv_bfloat16*)whi;  __nv_bfloat16* Wlo = (__nv_bfloat16*)wlo;
    __nv_bfloat16* Phi = (__nv_bfloat16*)phi;  __nv_bfloat16* Plo = (__nv_bfloat16*)plo;
    float* SIM = (float*)sim;

    cudaFuncSetAttribute(k_gemm<1>, cudaFuncAttributeMaxDynamicSharedMemorySize, GEMM_SMEM);
    cudaFuncSetAttribute(k_tc<0>,   cudaFuncAttributeMaxDynamicSharedMemorySize, SIM_SMEM);
    cudaFuncSetAttribute(k_tc<1>,   cudaFuncAttributeMaxDynamicSharedMemorySize, SIM_SMEM);

    float* conf = (float*)d_out;
    long long twoBST = 2LL * BST;
    int mode;
    if ((long long)out_size >= twoBST)             mode = 0;
    else if ((long long)out_size == BST + BST / 4) mode = 1;
    else                                           mode = 2;

    // launch indices: 0 masks, 1 prep3, 2 proj_tc, 3 proj_fb, 4 sim_fb, 5 sim_tc
    k_masks<<<(B_*S_ + 255) / 256, 256>>>(smk, tmk);
    k_prep3<<<(2*XN + C_*C_ + 255) / 256, 256>>>(src, tgt, W);
    // projection on tcgen05 (P = X @ W^T / 16, epilogue-split)
    k_tc<1><<<dim3(128, 1, 1), 256, SIM_SMEM>>>(
        Xhi, Xlo, Whi, Wlo, nullptr, Phi, Plo, 0.0625f);
    // projection fallback (skips when TC is live)
    k_gemm<1><<<dim3(2, 64, 2), 256, GEMM_SMEM>>>(
        Xhi, Xlo, (long long)XN, Whi, Wlo, 0LL,
        nullptr, Phi, Plo, (long long)XN, C_, C_, 0.0625f);
    // sim fallback (skips when TC is live; needs Phi from proj fallback)
    k_gemm<1><<<dim3(16, 16, 4), 256, GEMM_SMEM>>>(
        Phi, Plo, (long long)(S_*C_), Phi + XN, Plo + XN, (long long)(S_*C_),
        SIM, nullptr, nullptr, (long long)S_*T_, T_, C_, 10.f);
    // sim on tcgen05 (at ncu's -s 5 slot)
    k_tc<0><<<dim3(8, 16, 4), 256, SIM_SMEM>>>(
        Phi, Plo, Phi + XN, Plo + XN, SIM, nullptr, nullptr, 10.f);
    // softmax stats
    k_stats<<<dim3(64, B_), 256>>>();
    k_colcomb<<<(B_*T_ + 255) / 256, 256>>>();
    // conf + row max + col-max partials
    k_conf<<<dim3(64, B_), 256>>>(conf);
    k_cmaxcomb<<<(B_*T_ + 255) / 256, 256>>>();
    // match mask
    if (mode != 2) {
        float* mf = conf + BST;
        unsigned char* mb = (unsigned char*)d_out + (size_t)BST * 4;
        k_m<<<dim3(S_, B_), 256>>>(conf, mf, mb, mode);
    }
}

// round 10
// speedup vs baseline: 1.0312x; 1.0312x over previous
#include <cuda_runtime.h>
#include <cuda_bf16.h>
#include <stdint.h>
#include <math.h>

#define B_ 4
#define S_ 2048
#define T_ 2048
#define C_ 256
#define BST 16777216  // B_*S_*T_
#define XN  2097152   // B_*S_*C_
#define PN  4194304   // 2*B_*S_*C_

// ---- tcgen05 only legal when an sm_103a feature pass exists ----
#if defined(__CUDA_ARCH__) && defined(__CUDA_ARCH_FEAT_SM103_ALL)
#define HAS_TC 1
#else
#define HAS_TC 0
#endif

// ---------------- scratch (device globals; no runtime allocation) -------------
__device__ __nv_bfloat16 g_Xhi[PN];
__device__ __nv_bfloat16 g_Xlo[PN];
__device__ __nv_bfloat16 g_Whi[C_*C_];
__device__ __nv_bfloat16 g_Wlo[C_*C_];
__device__ __nv_bfloat16 g_Phi[PN];
__device__ __nv_bfloat16 g_Plo[PN];
__device__ float         g_sim[BST];

__device__ float g_Mrow[B_*S_], g_rZrow[B_*S_], g_Rmax[B_*S_];
__device__ int   g_Ridx[B_*S_];
__device__ float g_Mcol[B_*T_], g_rZcol[B_*T_], g_Cmax[B_*T_];
__device__ float g_pM[B_*64*T_], g_pZ[B_*64*T_];
__device__ unsigned char g_smask[B_*S_], g_tmask[B_*T_];

// ============================ PTX helpers =====================================
__device__ __forceinline__ uint32_t smem_u32(const void* p) {
    uint32_t a;
    asm("{ .reg .u64 t; cvta.to.shared.u64 t, %1; cvt.u32.u64 %0, t; }" : "=r"(a) : "l"(p));
    return a;
}
__device__ __forceinline__ void cp16(uint32_t dst, const void* src) {
    asm volatile("cp.async.cg.shared.global [%0], [%1], 16;\n" :: "r"(dst), "l"(src));
}
#define CP_COMMIT()  asm volatile("cp.async.commit_group;\n" ::: "memory")

#if HAS_TC
#define TC_ALLOC(smem_addr, n)   asm volatile("tcgen05.alloc.cta_group::1.sync.aligned.shared::cta.b32 [%0], %1;" :: "r"(smem_addr), "r"((uint32_t)(n)) : "memory")
#define TC_DEALLOC(tmem, n)      asm volatile("tcgen05.dealloc.cta_group::1.sync.aligned.b32 %0, %1;" :: "r"(tmem), "r"((uint32_t)(n)))
#define TC_RELINQ()              asm volatile("tcgen05.relinquish_alloc_permit.cta_group::1.sync.aligned;")
#define TC_COMMIT(mbar)          asm volatile("tcgen05.commit.cta_group::1.mbarrier::arrive::one.shared::cluster.b64 [%0];" :: "r"(mbar) : "memory")
#define TC_FENCE_AFTER()         asm volatile("tcgen05.fence::after_thread_sync;" ::: "memory")
#define TC_WAIT_LD()             asm volatile("tcgen05.wait::ld.sync.aligned;" ::: "memory")
#define FENCE_ASYNC_SHARED()     asm volatile("fence.proxy.async.shared::cta;" ::: "memory")
#define MBAR_INIT(a, c)          asm volatile("mbarrier.init.shared.b64 [%0], %1;" :: "r"(a), "r"((uint32_t)(c)) : "memory")
#define MBAR_INVAL(a)            asm volatile("mbarrier.inval.shared.b64 [%0];" :: "r"(a) : "memory")

#define MBAR_WAIT(a, par) do { \
    uint32_t _m = (a), _p = (par), _d; \
    asm volatile("{\n\t.reg .pred p;\n\t" \
        "mbarrier.try_wait.parity.acquire.cta.shared::cta.b64 p, [%1], %2;\n\t" \
        "selp.b32 %0, 1, 0, p;\n\t}" : "=r"(_d) : "r"(_m), "r"(_p) : "memory"); \
    if (!_d) { \
        asm volatile("{\n\t.reg .pred P1;\n\t" \
            "WL_%=:\n\t" \
            "mbarrier.try_wait.parity.acquire.cta.shared::cta.b64 P1, [%0], %1, 0x989680;\n\t" \
            "@P1 bra.uni WD_%=;\n\t" \
            "bra.uni WL_%=;\n\t" \
            "WD_%=:\n\t}" :: "r"(_m), "r"(_p) : "memory"); \
    } \
} while (0)

#define LDTM_X32(r, addr) \
    asm volatile("tcgen05.ld.sync.aligned.32x32b.x32.b32 " \
        "{%0,%1,%2,%3,%4,%5,%6,%7,%8,%9,%10,%11,%12,%13,%14,%15," \
        "%16,%17,%18,%19,%20,%21,%22,%23,%24,%25,%26,%27,%28,%29,%30,%31}, [%32];" \
        : "=r"((r)[0]), "=r"((r)[1]), "=r"((r)[2]), "=r"((r)[3]), \
          "=r"((r)[4]), "=r"((r)[5]), "=r"((r)[6]), "=r"((r)[7]), \
          "=r"((r)[8]), "=r"((r)[9]), "=r"((r)[10]), "=r"((r)[11]), \
          "=r"((r)[12]), "=r"((r)[13]), "=r"((r)[14]), "=r"((r)[15]), \
          "=r"((r)[16]), "=r"((r)[17]), "=r"((r)[18]), "=r"((r)[19]), \
          "=r"((r)[20]), "=r"((r)[21]), "=r"((r)[22]), "=r"((r)[23]), \
          "=r"((r)[24]), "=r"((r)[25]), "=r"((r)[26]), "=r"((r)[27]), \
          "=r"((r)[28]), "=r"((r)[29]), "=r"((r)[30]), "=r"((r)[31]) \
        : "r"(addr))

__device__ __forceinline__ uint32_t elect_one() {
    uint32_t p;
    asm volatile("{\n\t.reg .pred e;\n\telect.sync _|e, 0xFFFFFFFF;\n\t"
                 "selp.b32 %0, 1, 0, e;\n\t}" : "=r"(p));
    return p;
}
__device__ __forceinline__ uint64_t mk_desc(uint32_t addr) {
    const uint64_t base =
        (uint64_t(2) << 61) | (uint64_t(1) << 46) | (uint64_t(64) << 32) | (uint64_t(1) << 16);
    return base | ((uint64_t)(addr >> 4) & 0x3FFF);
}
__device__ __forceinline__ void umma_bf16_ss(uint32_t d, uint64_t a, uint64_t b,
                                             uint32_t idesc, uint32_t en) {
    asm volatile(
        "{\n\t.reg .pred p;\n\t"
        "setp.ne.u32 p, %4, 0;\n\t"
        "tcgen05.mma.cta_group::1.kind::f16 [%0], %1, %2, %3, {%5,%5,%5,%5}, p;\n\t}"
        :: "r"(d), "l"(a), "l"(b), "r"(idesc), "r"(en), "r"(0u)
        : "memory");
}
// fp32 accum, bf16 A/B, N=128, M=128
#define SIM_IDESC128 0x8200490u
#endif  // HAS_TC

// ------------- fused prep: masks + fp32->(hi,lo) splits for src, tgt, W ----------
__global__ void k_prep(const float* __restrict__ src, const float* __restrict__ tgt,
                       const float* __restrict__ W,
                       const unsigned char* __restrict__ smk,
                       const unsigned char* __restrict__ tmk) {
    int i = blockIdx.x * blockDim.x + threadIdx.x;
    if (i < B_*S_) {
        bool ws = (smk[1] == 0);
        bool wt = (tmk[1] == 0);
        g_smask[i] = ws ? (((const int*)smk)[i] != 0) : (smk[i] != 0);
        g_tmask[i] = wt ? (((const int*)tmk)[i] != 0) : (tmk[i] != 0);
    }
    const float* x; __nv_bfloat16 *hi, *lo; int off;
    if (i < XN)            { x = src; off = i;          hi = g_Xhi;      lo = g_Xlo; }
    else if (i < 2*XN)     { x = tgt; off = i - XN;     hi = g_Xhi + XN; lo = g_Xlo + XN; }
    else if (i < 2*XN + C_*C_) { x = W; off = i - 2*XN; hi = g_Whi;      lo = g_Wlo; }
    else return;
    float v = x[off];
    __nv_bfloat16 h = __float2bfloat16(v);
    hi[off] = h;
    lo[off] = __float2bfloat16(v - __bfloat162float(h));
}

// ============ tcgen05 GEMM: resident A + 2 interleaved N=128 tiles =================
// MODE 0 (sim):  grid (8,16,4); A = P-src rows, B = P-tgt rows, out = sim (fp32, x scale)
// MODE 1 (proj): grid (128);    A = X rows,     B = W,          out = Phi/Plo (split, x scale)
#define SIM_SMEM  230400
#define OFF_B     131072

template<int MODE>
__global__ __launch_bounds__(256, 1)
void k_tc(const __nv_bfloat16* __restrict__ Ah_g, const __nv_bfloat16* __restrict__ Al_g,
          const __nv_bfloat16* __restrict__ Bh_g, const __nv_bfloat16* __restrict__ Bl_g,
          float* __restrict__ simout, __nv_bfloat16* __restrict__ PhO,
          __nv_bfloat16* __restrict__ PlO, float scale)
{
#if HAS_TC
    extern __shared__ char ds[];
    __shared__ uint32_t s_tptr;
    __shared__ __align__(16) uint64_t s_mbar[2];

    const int tid = threadIdx.x, lane = tid & 31, wid = tid >> 5;
    const int bn = blockIdx.x, bm = (MODE == 0) ? blockIdx.y : blockIdx.x;
    const int z  = blockIdx.z;
    const uint32_t dsb = (smem_u32(ds) + 1023u) & ~1023u;   // SW128 needs 1024-aligned
    const uint32_t mb0 = smem_u32(&s_mbar[0]);
    const uint32_t mb1 = smem_u32(&s_mbar[1]);

    const char *Ahsrc, *Alsrc, *Bhsrc, *Blsrc;
    if (MODE == 0) {
        Ahsrc = (const char*)(Ah_g + ((size_t)z * S_ + bm * 128) * C_);
        Alsrc = (const char*)(Al_g + ((size_t)z * S_ + bm * 128) * C_);
        Bhsrc = (const char*)(Bh_g + ((size_t)z * T_ + bn * 256) * C_);
        Blsrc = (const char*)(Bl_g + ((size_t)z * T_ + bn * 256) * C_);
    } else {
        Ahsrc = (const char*)(Ah_g + (size_t)bm * 128 * C_);
        Alsrc = (const char*)(Al_g + (size_t)bm * 128 * C_);
        Bhsrc = (const char*)Bh_g;
        Blsrc = (const char*)Bl_g;
    }

    if (wid == 0) TC_ALLOC(smem_u32(&s_tptr), 256);
    if (tid == 0) { MBAR_INIT(mb0, 1); MBAR_INIT(mb1, 1); }
    __syncthreads();
    const uint32_t tmem = s_tptr;

    auto loadA = [&]() {
#pragma unroll
        for (int j = 0; j < 32; j++) {
            int c = tid + j * 256;
            int tile = c >> 10, idx = c & 1023;
            int row = idx >> 3, seg = idx & 7;
            const char* base = (tile < 4) ? Ahsrc : Alsrc;
            int kc = tile & 3;
            const char* s = base + (size_t)row * 512 + kc * 128 + seg * 16;
            uint32_t boff = (uint32_t)(row * 128 + seg * 16) ^ ((uint32_t)(row & 7) << 4);
            cp16(dsb + tile * 16384 + boff, s);
        }
        CP_COMMIT();
    };

    auto loadB = [&](int c) {   // chunk c: tc=c&1 (tile), q=c>>1 (0-3 hi, 4-7 lo)
        const int tc = c & 1, q = c >> 1, kc = q & 3, slot = c % 6;
        const char* base = ((q < 4) ? Bhsrc : Blsrc) + (size_t)tc * 128 * 512;
#pragma unroll
        for (int j = 0; j < 4; j++) {
            int cx = tid + j * 256;
            int row = cx >> 3, seg = cx & 7;
            const char* s = base + (size_t)row * 512 + kc * 128 + seg * 16;
            uint32_t boff = (uint32_t)(row * 128 + seg * 16) ^ ((uint32_t)(row & 7) << 4);
            cp16(dsb + OFF_B + slot * 16384 + boff, s);
        }
        CP_COMMIT();
    };

    loadB(0);
    loadA();
    loadB(1); loadB(2); loadB(3); loadB(4); loadB(5);

#pragma unroll
    for (int c = 0; c < 16; c++) {
        if (c >= 2) {
            const int k = c - 2;
            MBAR_WAIT((k & 1) ? mb1 : mb0, (k >> 1) & 1);
        }
        if (c >= 2 && c <= 11) loadB(c + 4);
        if (c == 0)       asm volatile("cp.async.wait_group 5;\n" ::: "memory");
        else if (c <= 11) asm volatile("cp.async.wait_group 4;\n" ::: "memory");
        else if (c == 12) asm volatile("cp.async.wait_group 3;\n" ::: "memory");
        else if (c == 13) asm volatile("cp.async.wait_group 2;\n" ::: "memory");
        else if (c == 14) asm volatile("cp.async.wait_group 1;\n" ::: "memory");
        else              asm volatile("cp.async.wait_group 0;\n" ::: "memory");
        __syncthreads();
        if (wid == 0) {
            if (elect_one()) {
                FENCE_ASYNC_SHARED();
                const int tc = c & 1, q = c >> 1, kc = q & 3, slot = c % 6;
                uint64_t ah = mk_desc(dsb + kc * 16384);
                uint64_t al = mk_desc(dsb + 65536 + kc * 16384);
                uint64_t bd = mk_desc(dsb + OFF_B + slot * 16384);
                uint32_t D = tmem + tc * 128;
                if (q < 4) {
#pragma unroll
                    for (int ks = 0; ks < 4; ks++) {
                        umma_bf16_ss(D, ah + ks * 2, bd + ks * 2, SIM_IDESC128,
                                     (q > 0) || (ks > 0));
                        umma_bf16_ss(D, al + ks * 2, bd + ks * 2, SIM_IDESC128, 1u);
                    }
                } else {
#pragma unroll
                    for (int ks = 0; ks < 4; ks++)
                        umma_bf16_ss(D, ah + ks * 2, bd + ks * 2, SIM_IDESC128, 1u);
                }
                TC_COMMIT((c & 1) ? mb1 : mb0);
            }
        }
    }
    MBAR_WAIT(mb0, 1);
    MBAR_WAIT(mb1, 1);

    TC_FENCE_AFTER();
    const int sub = wid & 3, half = (wid >> 2) * 128;
    if (MODE == 0) {
        float* out = simout + ((size_t)z * S_ + bm * 128 + sub * 32 + lane) * T_
                     + bn * 256 + half;
#pragma unroll
        for (int cb = 0; cb < 4; cb++) {
            uint32_t r[32];
            LDTM_X32(r, tmem + half + cb * 32);
            TC_WAIT_LD();
#pragma unroll
            for (int i = 0; i < 8; i++) {
                float4 v = make_float4(__uint_as_float(r[i*4+0]) * scale,
                                       __uint_as_float(r[i*4+1]) * scale,
                                       __uint_as_float(r[i*4+2]) * scale,
                                       __uint_as_float(r[i*4+3]) * scale);
                *reinterpret_cast<float4*>(out + cb * 32 + i * 4) = v;
            }
        }
    } else {
        size_t g = (size_t)(bm * 128 + sub * 32 + lane) * C_ + half;
#pragma unroll
        for (int cb = 0; cb < 4; cb++) {
            uint32_t r[32];
            LDTM_X32(r, tmem + half + cb * 32);
            TC_WAIT_LD();
#pragma unroll
            for (int i = 0; i < 8; i++) {
                float v0 = __uint_as_float(r[i*4+0]) * scale;
                float v1 = __uint_as_float(r[i*4+1]) * scale;
                float v2 = __uint_as_float(r[i*4+2]) * scale;
                float v3 = __uint_as_float(r[i*4+3]) * scale;
                __nv_bfloat16 h0 = __float2bfloat16(v0), h1 = __float2bfloat16(v1);
                __nv_bfloat16 h2 = __float2bfloat16(v2), h3 = __float2bfloat16(v3);
                __nv_bfloat162 hp01; hp01.x = h0; hp01.y = h1;
                __nv_bfloat162 hp23; hp23.x = h2; hp23.y = h3;
                __nv_bfloat162 lp01, lp23;
                lp01.x = __float2bfloat16(v0 - __bfloat162float(h0));
                lp01.y = __float2bfloat16(v1 - __bfloat162float(h1));
                lp23.x = __float2bfloat16(v2 - __bfloat162float(h2));
                lp23.y = __float2bfloat16(v3 - __bfloat162float(h3));
                size_t off = g + cb * 32 + i * 4;
                *reinterpret_cast<__nv_bfloat162*>(PhO + off)     = hp01;
                *reinterpret_cast<__nv_bfloat162*>(PhO + off + 2) = hp23;
                *reinterpret_cast<__nv_bfloat162*>(PlO + off)     = lp01;
                *reinterpret_cast<__nv_bfloat162*>(PlO + off + 2) = lp23;
            }
        }
    }

    __syncthreads();
    if (tid == 0) { MBAR_INVAL(mb0); MBAR_INVAL(mb1); }
    __syncthreads();
    if (wid == 0) { TC_RELINQ(); TC_DEALLOC(tmem, 256); }
#else
    (void)Ah_g; (void)Al_g; (void)Bh_g; (void)Bl_g;
    (void)simout; (void)PhO; (void)PlO; (void)scale;
#endif
}

// ---------------- block reductions ------------------------------------------------
__device__ __forceinline__ float bredMax(float v, float* sh) {
#pragma unroll
    for (int o = 16; o; o >>= 1) v = fmaxf(v, __shfl_xor_sync(0xffffffffu, v, o));
    if ((threadIdx.x & 31) == 0) sh[threadIdx.x >> 5] = v;
    __syncthreads();
    float r = sh[0];
#pragma unroll
    for (int i = 1; i < 8; i++) r = fmaxf(r, sh[i]);
    __syncthreads();
    return r;
}
__device__ __forceinline__ float bredSum(float v, float* sh) {
#pragma unroll
    for (int o = 16; o; o >>= 1) v += __shfl_xor_sync(0xffffffffu, v, o);
    if ((threadIdx.x & 31) == 0) sh[threadIdx.x >> 5] = v;
    __syncthreads();
    float r = sh[0];
#pragma unroll
    for (int i = 1; i < 8; i++) r += sh[i];
    __syncthreads();
    return r;
}

// ---------------- fused row stats (tgt-masked) + col partials (src-masked) -------
__global__ __launch_bounds__(256) void k_stats() {
    int b = blockIdx.y, ch = blockIdx.x, tid = threadIdx.x;
    int t0 = tid * 8;
    __shared__ float sh[8];
    bool tm[8]; float colM[8], colZ[8];
#pragma unroll
    for (int i = 0; i < 8; i++) {
        tm[i] = g_tmask[b * T_ + t0 + i];
        colM[i] = -INFINITY; colZ[i] = 0.f;
    }
    for (int r = 0; r < 32; r++) {
        int s = ch * 32 + r;
        const float4* row = (const float4*)(g_sim + ((size_t)b * S_ + s) * T_ + t0);
        float4 v0 = row[0], v1 = row[1];
        float x[8] = {v0.x, v0.y, v0.z, v0.w, v1.x, v1.y, v1.z, v1.w};
        float m = -INFINITY;
#pragma unroll
        for (int i = 0; i < 8; i++) if (tm[i]) m = fmaxf(m, x[i]);
        m = bredMax(m, sh);
        float zz = 0.f;
#pragma unroll
        for (int i = 0; i < 8; i++) if (tm[i]) zz += __expf(x[i] - m);
        zz = bredSum(zz, sh);
        if (tid == 0) { g_Mrow[b * S_ + s] = m; g_rZrow[b * S_ + s] = 1.f / zz; }
        if (g_smask[b * S_ + s]) {
#pragma unroll
            for (int i = 0; i < 8; i++) {
                float mn = fmaxf(colM[i], x[i]);
                colZ[i] = colZ[i] * __expf(colM[i] - mn) + __expf(x[i] - mn);
                colM[i] = mn;
            }
        }
    }
    size_t o = (size_t)(b * 64 + ch) * T_ + t0;
#pragma unroll
    for (int i = 0; i < 8; i++) { g_pM[o + i] = colM[i]; g_pZ[o + i] = colZ[i]; }
}

__global__ void k_colcomb() {
    int i = blockIdx.x * blockDim.x + threadIdx.x;
    if (i >= B_ * T_) return;
    int b = i >> 11, t = i & 2047;
    float M = -INFINITY;
    for (int c = 0; c < 64; c++) M = fmaxf(M, g_pM[(size_t)(b * 64 + c) * T_ + t]);
    float Z = 0.f;
    for (int c = 0; c < 64; c++) {
        float m = g_pM[(size_t)(b * 64 + c) * T_ + t];
        Z += g_pZ[(size_t)(b * 64 + c) * T_ + t] * __expf(m - M);
    }
    g_Mcol[i] = M; g_rZcol[i] = 1.f / Z;
}

// --------- conf + per-row (max, argmax) + col-max partials (fused) ----------------
__global__ __launch_bounds__(256) void k_conf(float* __restrict__ conf) {
    int b = blockIdx.y, ch = blockIdx.x, tid = threadIdx.x;
    int lane = tid & 31, wid = tid >> 5;
    int t0 = tid * 8;
    __shared__ float shv[8];
    __shared__ int   shi[8];
    float mc[8], rzc[8], cm[8]; bool tm[8];
#pragma unroll
    for (int i = 0; i < 8; i++) {
        mc[i] = g_Mcol[b * T_ + t0 + i];
        rzc[i] = g_rZcol[b * T_ + t0 + i];
        tm[i] = g_tmask[b * T_ + t0 + i];
        cm[i] = 0.f;
    }
    for (int r = 0; r < 32; r++) {
        int s = ch * 32 + r;
        bool sv = g_smask[b * S_ + s];
        float Mr = g_Mrow[b * S_ + s], rZr = g_rZrow[b * S_ + s];
        size_t off = ((size_t)b * S_ + s) * T_ + t0;
        const float4* row = (const float4*)(g_sim + off);
        float4 v0 = row[0], v1 = row[1];
        float x[8] = {v0.x, v0.y, v0.z, v0.w, v1.x, v1.y, v1.z, v1.w};
        float v[8]; float rm = 0.f; int ri = t0;
#pragma unroll
        for (int i = 0; i < 8; i++) {
            float val = 0.f;
            if (sv && tm[i])
                val = __expf(2.f * x[i] - Mr - mc[i]) * rZr * rzc[i];
            v[i] = val;
            if (val > rm) { rm = val; ri = t0 + i; }
            cm[i] = fmaxf(cm[i], val);
        }
        float4 o0 = make_float4(v[0], v[1], v[2], v[3]);
        float4 o1 = make_float4(v[4], v[5], v[6], v[7]);
        float4* outp = (float4*)(conf + off);
        outp[0] = o0; outp[1] = o1;
        // block (max, argmax) reduce
#pragma unroll
        for (int o = 16; o; o >>= 1) {
            float ov = __shfl_xor_sync(0xffffffffu, rm, o);
            int   oi = __shfl_xor_sync(0xffffffffu, ri, o);
            if (ov > rm) { rm = ov; ri = oi; }
        }
        if (lane == 0) { shv[wid] = rm; shi[wid] = ri; }
        __syncthreads();
        float bv = shv[0]; int bi = shi[0];
#pragma unroll
        for (int k = 1; k < 8; k++)
            if (shv[k] > bv) { bv = shv[k]; bi = shi[k]; }
        __syncthreads();
        if (tid == 0) { g_Rmax[b * S_ + s] = bv; g_Ridx[b * S_ + s] = bi; }
    }
    size_t o = (size_t)(b * 64 + ch) * T_ + t0;
#pragma unroll
    for (int i = 0; i < 8; i++) g_pM[o + i] = cm[i];
}

__global__ void k_cmaxcomb() {
    int i = blockIdx.x * blockDim.x + threadIdx.x;
    if (i >= B_ * T_) return;
    int b = i >> 11, t = i & 2047;
    float m = 0.f;
    for (int c = 0; c < 64; c++) m = fmaxf(m, g_pM[(size_t)(b * 64 + c) * T_ + t]);
    g_Cmax[i] = m;
}

// ---------------- m = mutual-max mask: zero fill + sparse scatter ------------------
__global__ void k_mzero(uint4* __restrict__ p, long long n16) {
    long long i = (long long)blockIdx.x * blockDim.x + threadIdx.x;
    if (i < n16) p[i] = make_uint4(0u, 0u, 0u, 0u);
}
__global__ void k_mscatter(float* __restrict__ mf, unsigned char* __restrict__ mb,
                           int mode) {
    int i = blockIdx.x * blockDim.x + threadIdx.x;
    if (i >= B_ * S_) return;
    int b = i >> 11;
    float v = g_Rmax[i];
    int t = g_Ridx[i];
    if (v > 0.2f && v == g_Cmax[b * T_ + t]) {
        size_t off = (size_t)i * T_ + t;
        if (mode == 0) mf[off] = 1.f;
        else           mb[off] = 1;
    }
}

// ---------------- launch -------------------------------------------------------------
extern "C" void kernel_launch(void* const* d_in, const int* in_sizes, int n_in,
                              void* d_out, int out_size) {
    const float *src = nullptr, *tgt = nullptr, *W = nullptr;
    const unsigned char *smk = nullptr, *tmk = nullptr;
    for (int i = 0; i < n_in; i++) {
        if (in_sizes[i] == XN)        { if (!src) src = (const float*)d_in[i]; else tgt = (const float*)d_in[i]; }
        else if (in_sizes[i] == 8192) { if (!smk) smk = (const unsigned char*)d_in[i]; else tmk = (const unsigned char*)d_in[i]; }
        else if (in_sizes[i] == 65536) W = (const float*)d_in[i];
    }

    void *xhi, *xlo, *whi, *wlo, *phi, *plo, *sim;
    cudaGetSymbolAddress(&xhi, g_Xhi);  cudaGetSymbolAddress(&xlo, g_Xlo);
    cudaGetSymbolAddress(&whi, g_Whi);  cudaGetSymbolAddress(&wlo, g_Wlo);
    cudaGetSymbolAddress(&phi, g_Phi);  cudaGetSymbolAddress(&plo, g_Plo);
    cudaGetSymbolAddress(&sim, g_sim);

    __nv_bfloat16* Xhi = (__nv_bfloat16*)xhi;  __nv_bfloat16* Xlo = (__nv_bfloat16*)xlo;
    __nv_bfloat16* Whi = (__nv_bfloat16*)whi;  __nv_bfloat16* Wlo = (__nv_bfloat16*)wlo;
    __nv_bfloat16* Phi = (__nv_bfloat16*)phi;  __nv_bfloat16* Plo = (__nv_bfloat16*)plo;
    float* SIM = (float*)sim;

    cudaFuncSetAttribute(k_tc<0>, cudaFuncAttributeMaxDynamicSharedMemorySize, SIM_SMEM);
    cudaFuncSetAttribute(k_tc<1>, cudaFuncAttributeMaxDynamicSharedMemorySize, SIM_SMEM);

    float* conf = (float*)d_out;
    long long twoBST = 2LL * BST;
    int mode;
    if ((long long)out_size >= twoBST)             mode = 0;
    else if ((long long)out_size == BST + BST / 4) mode = 1;
    else                                           mode = 2;

    // launch idx: 0 prep, 1 proj_tc, 2 sim_tc, 3 stats, 4 colcomb, 5 conf (ncu -s 5)
    k_prep<<<(2*XN + C_*C_ + 255) / 256, 256>>>(src, tgt, W, smk, tmk);
    k_tc<1><<<dim3(128, 1, 1), 256, SIM_SMEM>>>(
        Xhi, Xlo, Whi, Wlo, nullptr, Phi, Plo, 0.0625f);
    k_tc<0><<<dim3(8, 16, 4), 256, SIM_SMEM>>>(
        Phi, Plo, Phi + XN, Plo + XN, SIM, nullptr, nullptr, 10.f);
    k_stats<<<dim3(64, B_), 256>>>();
    k_colcomb<<<(B_*T_ + 255) / 256, 256>>>();
    k_conf<<<dim3(64, B_), 256>>>(conf);
    k_cmaxcomb<<<(B_*T_ + 255) / 256, 256>>>();
    if (mode != 2) {
        float* mf = conf + BST;
        unsigned char* mb = (unsigned char*)d_out + (size_t)BST * 4;
        long long n16 = (mode == 0) ? ((long long)BST * 4 / 16) : ((long long)BST / 16);
        uint4* zp = (mode == 0) ? (uint4*)mf : (uint4*)mb;
        k_mzero<<<(unsigned)((n16 + 255) / 256), 256>>>(zp, n16);
        k_mscatter<<<(B_*S_ + 255) / 256, 256>>>(mf, mb, mode);
    }
}